// round 6
// baseline (speedup 1.0000x reference)
#include <cuda_runtime.h>
#include <cuda_bf16.h>
#include <math.h>
#include <stdint.h>

// ---------------- problem constants ----------------
#define S_LEN 1024
#define H_DIM 768
#define L_LAB 50
#define SW_WIN 10
#define D_DIM 2304            // 3*H
#define NMAX 16384
#define KT2 32                // K per pipeline stage
#define LDK2 40               // padded smem row (elems)
#define KEEP 416

// ---------------- scratch (device globals) ----------------
__device__ float g_T[L_LAB*S_LEN*H_DIM];     // per-label transformed x
__device__ float g_cnt[S_LEN*L_LAB];
__device__ float g_out1[S_LEN*H_DIM];
__device__ float g_emb[S_LEN*H_DIM];
__device__ float g_P[3*S_LEN*D_DIM];
__device__ float g_q[7*S_LEN];
__device__ float g_aw[NMAX*SW_WIN];
__device__ float g_si[NMAX];
__device__ float g_sj[NMAX];
__device__ float g_ms[NMAX];
__device__ int   g_idx[1024];
__device__ unsigned long long g_skeys[16*KEEP];
__device__ int   g_estart[1025];
__device__ int   g_ecur[1024];
__device__ int   g_epack[1 << 17];           // packed T-row index per edge (bucketed by tgt)

__device__ __nv_bfloat16 g_Xhi[S_LEN*H_DIM];
__device__ __nv_bfloat16 g_Xlo[S_LEN*H_DIM];
__device__ __nv_bfloat16 g_Bhi[L_LAB*H_DIM*H_DIM];   // W_l^T per label [l][d][h]
__device__ __nv_bfloat16 g_Blo[L_LAB*H_DIM*H_DIM];
__device__ __nv_bfloat16 g_W1thi[D_DIM*D_DIM];       // ms_W1^T [n][k]
__device__ __nv_bfloat16 g_W1tlo[D_DIM*D_DIM];
__device__ __nv_bfloat16 g_Ehi[S_LEN*H_DIM];
__device__ __nv_bfloat16 g_Elo[S_LEN*H_DIM];

// ---------------- cp.async / ldmatrix helpers ----------------
#define CP_ASYNC16(saddr, gptr) \
    asm volatile("cp.async.cg.shared.global [%0], [%1], 16;" :: "r"(saddr), "l"(gptr) : "memory")
#define CP_COMMIT() asm volatile("cp.async.commit_group;" ::: "memory")
#define CP_WAIT1()  asm volatile("cp.async.wait_group 1;" ::: "memory")
#define CP_WAIT0()  asm volatile("cp.async.wait_group 0;" ::: "memory")

__device__ __forceinline__ void ldsm_x4(uint32_t& r0, uint32_t& r1, uint32_t& r2, uint32_t& r3,
                                        uint32_t addr) {
    asm volatile("ldmatrix.sync.aligned.m8n8.x4.shared.b16 {%0,%1,%2,%3}, [%4];"
        : "=r"(r0), "=r"(r1), "=r"(r2), "=r"(r3) : "r"(addr));
}

__device__ __forceinline__ void mma16816(float* c, const uint32_t* a, const uint32_t* b) {
    asm volatile("mma.sync.aligned.m16n8k16.row.col.f32.bf16.bf16.f32 "
        "{%0,%1,%2,%3}, {%4,%5,%6,%7}, {%8,%9}, {%0,%1,%2,%3};"
        : "+f"(c[0]), "+f"(c[1]), "+f"(c[2]), "+f"(c[3])
        : "r"(a[0]), "r"(a[1]), "r"(a[2]), "r"(a[3]), "r"(b[0]), "r"(b[1]));
}

// ---------------- edge bucketing ----------------
__global__ void cnt_kernel(const int* __restrict__ edges, int E) {
    int e = blockIdx.x * blockDim.x + threadIdx.x;
    if (e >= E) return;
    atomicAdd(&g_cnt[edges[3*e + 1] * L_LAB + edges[3*e + 2]], 1.0f);
}

// per-tgt histogram from g_cnt row sums + exclusive scan
__global__ void scan_kernel() {
    __shared__ int sh[1024];
    int tid = threadIdx.x;
    float fv = 0.f;
#pragma unroll
    for (int l = 0; l < L_LAB; l++) fv += g_cnt[tid * L_LAB + l];
    int v = (int)(fv + 0.5f);
    sh[tid] = v;
    __syncthreads();
    for (int off = 1; off < 1024; off <<= 1) {
        int t = (tid >= off) ? sh[tid - off] : 0;
        __syncthreads();
        sh[tid] += t;
        __syncthreads();
    }
    g_estart[tid + 1] = sh[tid];
    if (tid == 0) g_estart[0] = 0;
    g_ecur[tid] = sh[tid] - v;    // bucket cursor (exclusive prefix)
}

__global__ void place_kernel(const int* __restrict__ edges, int E) {
    int e = blockIdx.x * blockDim.x + threadIdx.x;
    if (e >= E) return;
    int pos = atomicAdd(&g_ecur[edges[3*e + 1]], 1);
    g_epack[pos] = edges[3*e + 2] * S_LEN + edges[3*e];   // T row = lbl*1024 + src
}

// ---------------- fp32 -> bf16 hi/lo split ----------------
__global__ void cvt_split_kernel(const float* __restrict__ src,
                                 __nv_bfloat16* __restrict__ hi,
                                 __nv_bfloat16* __restrict__ lo, int n4) {
    int i = blockIdx.x * blockDim.x + threadIdx.x;
    if (i >= n4) return;
    float4 v = ((const float4*)src)[i];
    __nv_bfloat16 h0 = __float2bfloat16_rn(v.x);
    __nv_bfloat16 h1 = __float2bfloat16_rn(v.y);
    __nv_bfloat16 h2 = __float2bfloat16_rn(v.z);
    __nv_bfloat16 h3 = __float2bfloat16_rn(v.w);
    __nv_bfloat16 l0 = __float2bfloat16_rn(v.x - __bfloat162float(h0));
    __nv_bfloat16 l1 = __float2bfloat16_rn(v.y - __bfloat162float(h1));
    __nv_bfloat16 l2 = __float2bfloat16_rn(v.z - __bfloat162float(h2));
    __nv_bfloat16 l3 = __float2bfloat16_rn(v.w - __bfloat162float(h3));
    __nv_bfloat162* hp = (__nv_bfloat162*)hi;
    __nv_bfloat162* lp = (__nv_bfloat162*)lo;
    hp[2*i]   = __nv_bfloat162(h0, h1);
    hp[2*i+1] = __nv_bfloat162(h2, h3);
    lp[2*i]   = __nv_bfloat162(l0, l1);
    lp[2*i+1] = __nv_bfloat162(l2, l3);
}

// ---- batched transpose+split: src[b][r][c] -> dst[b][c][r], bf16 hi/lo ----
__global__ void transpose_split_kernel(const float* __restrict__ src,
                                       __nv_bfloat16* __restrict__ hi,
                                       __nv_bfloat16* __restrict__ lo,
                                       int R, int C) {
    __shared__ float t[32][33];
    int b = blockIdx.z;
    int c0 = blockIdx.x * 32, r0 = blockIdx.y * 32;
    int tx = threadIdx.x, ty = threadIdx.y;
    size_t sbase = (size_t)b * R * C;
    t[ty][tx] = src[sbase + (size_t)(r0 + ty) * C + c0 + tx];
    __syncthreads();
    float v = t[tx][ty];
    __nv_bfloat16 h = __float2bfloat16_rn(v);
    __nv_bfloat16 l = __float2bfloat16_rn(v - __bfloat162float(h));
    size_t o = sbase + (size_t)(c0 + ty) * R + r0 + tx;
    hi[o] = h;
    lo[o] = l;
}

// ---------------- mma.sync bf16 split GEMM (cp.async + ldmatrix) ------------
// C[bz*cOff + (bm*128+r)*ldC + bn*128+c] (+)= A(128 x K) * B(128 x K)^T
__global__ __launch_bounds__(256, 2)
void mma_gemm_kernel(const __nv_bfloat16* __restrict__ Ahi, const __nv_bfloat16* __restrict__ Alo,
                     const __nv_bfloat16* __restrict__ Bhi, const __nv_bfloat16* __restrict__ Blo,
                     float* __restrict__ C, int ldA, int ldB, int ldC,
                     int ktiles, long long aOff, long long bOff, long long cOff, int atomic) {
    extern __shared__ __nv_bfloat16 sm[];   // 2 stages x 4 arrays x 128*LDK2
    uint32_t smb = (uint32_t)__cvta_generic_to_shared(sm);

    int tid = threadIdx.x;
    int wid = tid >> 5, lane = tid & 31;
    int wm = wid >> 2, wn = wid & 3;        // warp grid 2x4, warp tile 64x32
    int bn = blockIdx.x, bm = blockIdx.y, bz = blockIdx.z;

    const __nv_bfloat16* Ah = Ahi + (size_t)bm * 128 * ldA + (size_t)bz * aOff;
    const __nv_bfloat16* Al = Alo + (size_t)bm * 128 * ldA + (size_t)bz * aOff;
    const __nv_bfloat16* Bh = Bhi + (size_t)bn * 128 * ldB + (size_t)bz * bOff;
    const __nv_bfloat16* Bl = Blo + (size_t)bn * 128 * ldB + (size_t)bz * bOff;

    float acc[4][4][4];
#pragma unroll
    for (int i = 0; i < 4; i++)
#pragma unroll
        for (int j = 0; j < 4; j++)
#pragma unroll
            for (int r = 0; r < 4; r++) acc[i][j][r] = 0.f;

    const int STAGE = 4 * 128 * LDK2;       // elems per stage

#define ISSUE(stg, t) do {                                                     \
        int k0 = (t) * KT2;                                                    \
        uint32_t sbase = smb + (stg) * STAGE * 2;                              \
        _Pragma("unroll")                                                      \
        for (int i = 0; i < 8; i++) {                                          \
            int o = tid + i * 256;                                             \
            int arr = o >> 9;                                                  \
            int rem = o & 511;                                                 \
            int row = rem >> 2;                                                \
            int quad = rem & 3;                                                \
            const __nv_bfloat16* src; int ld;                                  \
            if (arr == 0)      { src = Ah; ld = ldA; }                         \
            else if (arr == 1) { src = Al; ld = ldA; }                         \
            else if (arr == 2) { src = Bh; ld = ldB; }                         \
            else               { src = Bl; ld = ldB; }                         \
            const void* g = src + (size_t)row * ld + k0 + quad * 8;            \
            uint32_t sa = sbase + (uint32_t)(arr * 128 * LDK2 + row * LDK2 + quad * 8) * 2; \
            CP_ASYNC16(sa, g);                                                 \
        }                                                                      \
    } while (0)

    ISSUE(0, 0);
    CP_COMMIT();

    // precomputed ldmatrix lane address offsets (elements within an array)
    int grp = lane >> 3, l7 = lane & 7;
    int aRow = (grp & 1) * 8 + l7;          // + wm*64 + mi*16
    int aKel = (grp >> 1) * 8;              // + ks*16
    int bRow = (grp >> 1) * 8 + l7;         // + wn*32 + pr*16
    int bKel = (grp & 1) * 8;               // + ks*16

    for (int t = 0; t < ktiles; t++) {
        int s = t & 1;
        if (t + 1 < ktiles) {
            ISSUE(s ^ 1, t + 1);
            CP_COMMIT();
            CP_WAIT1();
        } else {
            CP_WAIT0();
        }
        __syncthreads();

        uint32_t sAh = smb + (uint32_t)(s * STAGE) * 2;
        uint32_t sAl = sAh + 128 * LDK2 * 2;
        uint32_t sBh = sAh + 2 * 128 * LDK2 * 2;
        uint32_t sBl = sAh + 3 * 128 * LDK2 * 2;

#pragma unroll
        for (int ks = 0; ks < 2; ks++) {
            uint32_t bh[4][2], bl[4][2];
#pragma unroll
            for (int pr = 0; pr < 2; pr++) {
                uint32_t off = (uint32_t)((wn * 32 + pr * 16 + bRow) * LDK2
                                          + ks * 16 + bKel) * 2;
                ldsm_x4(bh[2*pr][0], bh[2*pr][1], bh[2*pr+1][0], bh[2*pr+1][1], sBh + off);
                ldsm_x4(bl[2*pr][0], bl[2*pr][1], bl[2*pr+1][0], bl[2*pr+1][1], sBl + off);
            }
#pragma unroll
            for (int mi = 0; mi < 4; mi++) {
                uint32_t off = (uint32_t)((wm * 64 + mi * 16 + aRow) * LDK2
                                          + ks * 16 + aKel) * 2;
                uint32_t ah[4], al[4];
                ldsm_x4(ah[0], ah[1], ah[2], ah[3], sAh + off);
                ldsm_x4(al[0], al[1], al[2], al[3], sAl + off);
#pragma unroll
                for (int ni = 0; ni < 4; ni++) {
                    mma16816(acc[mi][ni], ah, bh[ni]);
                    mma16816(acc[mi][ni], ah, bl[ni]);
                    mma16816(acc[mi][ni], al, bh[ni]);
                }
            }
        }
        __syncthreads();
    }

    float* Cb = C + (size_t)bz * cOff + (size_t)bm * 128 * ldC + (size_t)bn * 128;
#pragma unroll
    for (int mi = 0; mi < 4; mi++) {
#pragma unroll
        for (int ni = 0; ni < 4; ni++) {
            int r = wm * 64 + mi * 16 + (lane >> 2);
            int cc = wn * 32 + ni * 8 + (lane & 3) * 2;
            float* p0 = Cb + (size_t)r * ldC + cc;
            float* p1 = Cb + (size_t)(r + 8) * ldC + cc;
            if (atomic) {
                atomicAdd(p0,     acc[mi][ni][0]);
                atomicAdd(p0 + 1, acc[mi][ni][1]);
                atomicAdd(p1,     acc[mi][ni][2]);
                atomicAdd(p1 + 1, acc[mi][ni][3]);
            } else {
                *(float2*)p0 = make_float2(acc[mi][ni][0], acc[mi][ni][1]);
                *(float2*)p1 = make_float2(acc[mi][ni][2], acc[mi][ni][3]);
            }
        }
    }
#undef ISSUE
}

// ---------------- gather: out1[s] = sum_e T[row_e] (packed rows) ------------
__global__ void gather_kernel(int dummy) {
    int s = blockIdx.x;
    int tid = threadIdx.x;  // 192 (= 768/4)
    int beg = g_estart[s], end = g_estart[s + 1];
    float4 acc = make_float4(0.f, 0.f, 0.f, 0.f);
    int p = beg;
    for (; p + 4 <= end; p += 4) {
        int r0 = g_epack[p], r1 = g_epack[p + 1], r2 = g_epack[p + 2], r3 = g_epack[p + 3];
        float4 v0 = __ldg(((const float4*)(g_T + (size_t)r0 * H_DIM)) + tid);
        float4 v1 = __ldg(((const float4*)(g_T + (size_t)r1 * H_DIM)) + tid);
        float4 v2 = __ldg(((const float4*)(g_T + (size_t)r2 * H_DIM)) + tid);
        float4 v3 = __ldg(((const float4*)(g_T + (size_t)r3 * H_DIM)) + tid);
        acc.x += (v0.x + v1.x) + (v2.x + v3.x);
        acc.y += (v0.y + v1.y) + (v2.y + v3.y);
        acc.z += (v0.z + v1.z) + (v2.z + v3.z);
        acc.w += (v0.w + v1.w) + (v2.w + v3.w);
    }
    for (; p < end; p++) {
        int r0 = g_epack[p];
        float4 v0 = __ldg(((const float4*)(g_T + (size_t)r0 * H_DIM)) + tid);
        acc.x += v0.x; acc.y += v0.y; acc.z += v0.z; acc.w += v0.w;
    }
    ((float4*)(g_out1 + (size_t)s * H_DIM))[tid] = acc;
}

// ---------------- GCN epilogue ----------------
__global__ void gcn_epi_kernel(const float* __restrict__ x,
                               const float* __restrict__ gcn_b) {
    int s = blockIdx.x, tid = threadIdx.x;
    __shared__ float c[L_LAB];
    if (tid < L_LAB) c[tid] = g_cnt[s * L_LAB + tid];
    __syncthreads();
    float deg = 0.f;
#pragma unroll
    for (int l = 0; l < L_LAB; l++) deg += c[l];
    deg = fmaxf(deg, 1.0f);
    float inv = 1.0f / deg;
    for (int d = tid; d < H_DIM; d += blockDim.x) {
        float bias = 0.f;
#pragma unroll
        for (int l = 0; l < L_LAB; l++) bias += c[l] * gcn_b[l * H_DIM + d];
        float v = (g_out1[s * H_DIM + d] + bias) * inv;
        g_emb[s * H_DIM + d] = x[s * H_DIM + d] + fmaxf(v, 0.f);
    }
}

// ---------------- q tables ----------------
__global__ void qdot_kernel(const float* __restrict__ antW,
                            const float* __restrict__ attn_w) {
    int wid = (blockIdx.x * blockDim.x + threadIdx.x) >> 5;
    int lane = threadIdx.x & 31;
    if (wid >= 7 * S_LEN) return;
    int t = wid >> 10;
    int s = wid & 1023;
    const float* v = (t < 6) ? (antW + t * H_DIM) : attn_w;
    float p = 0.f;
    for (int h = lane; h < H_DIM; h += 32) p += g_emb[s * H_DIM + h] * v[h];
#pragma unroll
    for (int off = 16; off; off >>= 1) p += __shfl_xor_sync(0xffffffffu, p, off);
    if (lane == 0) g_q[t * S_LEN + s] = p;
}

// ---------------- span attention from score table ---------------------------
__global__ void span_kernel(const int* __restrict__ ssp, const int* __restrict__ sep,
                            const float* __restrict__ attn_b, int Nspan) {
    int n = blockIdx.x * blockDim.x + threadIdx.x;
    if (n >= Nspan) return;
    int ss = ssp[n], se = sep[n];
    float sc[SW_WIN];
#pragma unroll
    for (int w = 0; w < SW_WIN; w++) {
        int pos = ss + w;
        int pc = min(pos, S_LEN - 1);
        sc[w] = (pos <= se) ? (g_q[6 * S_LEN + pc] + attn_b[0]) : -1e9f;
    }
    float mx = sc[0];
#pragma unroll
    for (int w = 1; w < SW_WIN; w++) mx = fmaxf(mx, sc[w]);
    float aw[SW_WIN], Z = 0.f;
#pragma unroll
    for (int w = 0; w < SW_WIN; w++) { aw[w] = expf(sc[w] - mx); Z += aw[w]; }
    float inv = 1.0f / Z;
#pragma unroll
    for (int w = 0; w < SW_WIN; w++) aw[w] *= inv;
    float si = g_q[0 * S_LEN + ss] + g_q[1 * S_LEN + se];
    float sj = g_q[3 * S_LEN + ss] + g_q[4 * S_LEN + se];
#pragma unroll
    for (int w = 0; w < SW_WIN; w++) {
        g_aw[n * SW_WIN + w] = aw[w];
        int pc = min(ss + w, S_LEN - 1);
        si += aw[w] * g_q[2 * S_LEN + pc];
        sj += aw[w] * g_q[5 * S_LEN + pc];
    }
    g_si[n] = si;
    g_sj[n] = sj;
}

// ---------------- mention scores, grouped by span start ---------------------
__global__ void mention2_kernel(const float* __restrict__ b1,
                                const float* __restrict__ W2,
                                const float* __restrict__ b2) {
    int s = blockIdx.x;
    int tid = threadIdx.x;      // 256
    extern __shared__ float sh[];
    float* sP3 = sh;                    // [10][D_DIM]
    float* sP1 = sh + 10 * D_DIM;       // [D_DIM]
    __shared__ float red[8];

    const float4* P3base = (const float4*)(g_P + (size_t)2 * S_LEN * D_DIM);
#pragma unroll
    for (int w = 0; w < SW_WIN; w++) {
        int pc = min(s + w, S_LEN - 1);
        const float4* srcp = P3base + (size_t)pc * (D_DIM / 4);
        float4* dstp = (float4*)(sP3 + w * D_DIM);
        for (int j = tid; j < D_DIM / 4; j += 256) dstp[j] = srcp[j];
    }
    {
        const float4* srcp = (const float4*)(g_P + (size_t)s * D_DIM);
        float4* dstp = (float4*)sP1;
        for (int j = tid; j < D_DIM / 4; j += 256) dstp[j] = srcp[j];
    }
    __syncthreads();

    int nsp, base;
    if (s <= 1014) { nsp = 9; base = 9 * s; }
    else { int u = s - 1015; nsp = 1023 - s; base = 9135 + u * (17 - u) / 2; }

    for (int sp = 0; sp < nsp; sp++) {
        int n = base + sp;
        int e = s + 1 + sp;
        float aw[SW_WIN];
#pragma unroll
        for (int w = 0; w < SW_WIN; w++) aw[w] = g_aw[n * SW_WIN + w];
        const float* P2 = g_P + ((size_t)S_LEN + e) * D_DIM;
        float part = 0.f;
        for (int j = tid; j < D_DIM; j += 256) {
            float v = sP1[j] + P2[j] + b1[j];
#pragma unroll
            for (int w = 0; w < SW_WIN; w++) v += aw[w] * sP3[w * D_DIM + j];
            part += fmaxf(v, 0.f) * W2[j];
        }
#pragma unroll
        for (int off = 16; off; off >>= 1) part += __shfl_xor_sync(0xffffffffu, part, off);
        if ((tid & 31) == 0) red[tid >> 5] = part;
        __syncthreads();
        if (tid < 8) {
            float v2 = red[tid];
#pragma unroll
            for (int off = 4; off; off >>= 1) v2 += __shfl_xor_sync(0xffu, v2, off);
            if (tid == 0) g_ms[n] = v2 + b2[0];
        }
        __syncthreads();
    }
}

// ---------------- top-k: two-stage bitonic ----------------------------------
__device__ __forceinline__ unsigned long long enc_key(float f, int i) {
    unsigned u = __float_as_uint(f);
    unsigned m = (u & 0x80000000u) ? ~u : (u | 0x80000000u);
    return (((unsigned long long)(~m)) << 32) | (unsigned)i;
}

__global__ void sort1_kernel(int Nspan) {
    __shared__ unsigned long long k[1024];
    int b = blockIdx.x, tid = threadIdx.x;
    int i = b * 1024 + tid;
    k[tid] = (i < Nspan) ? enc_key(g_ms[i], i) : ~0ull;
    __syncthreads();
    for (int sz = 2; sz <= 1024; sz <<= 1) {
        for (int j = sz >> 1; j; j >>= 1) {
            int ixj = tid ^ j;
            if (ixj > tid) {
                bool up = ((tid & sz) == 0);
                unsigned long long a = k[tid], c = k[ixj];
                if ((a > c) == up) { k[tid] = c; k[ixj] = a; }
            }
            __syncthreads();
        }
    }
    if (tid < KEEP) g_skeys[b * KEEP + tid] = k[tid];
}

__global__ void sort2_kernel(int Ktop) {
    extern __shared__ unsigned long long k2[];
    const int n = 8192;
    int tid = threadIdx.x;
    for (int i = tid; i < n; i += 1024)
        k2[i] = (i < 16 * KEEP) ? g_skeys[i] : ~0ull;
    __syncthreads();
    for (int sz = 2; sz <= n; sz <<= 1) {
        for (int j = sz >> 1; j; j >>= 1) {
            for (int i = tid; i < n; i += 1024) {
                int ixj = i ^ j;
                if (ixj > i) {
                    bool up = ((i & sz) == 0);
                    unsigned long long a = k2[i], c = k2[ixj];
                    if ((a > c) == up) { k2[i] = c; k2[ixj] = a; }
                }
            }
            __syncthreads();
        }
    }
    for (int i = tid; i < Ktop; i += 1024) g_idx[i] = (int)(k2[i] & 0xFFFFFFFFu);
}

// ---------------- final antecedent matrix -----------------------------------
__global__ void final_kernel(const float* __restrict__ ant_b, float* __restrict__ out,
                             int Ktop, int total) {
    int p = blockIdx.x * blockDim.x + threadIdx.x;
    if (p >= total) return;
    int cols = Ktop + 1;
    int i = p / cols;
    int c = p - i * cols;
    float v;
    if (c == 0) v = 0.0f;
    else {
        int j = c - 1;
        v = (j >= i) ? -10000.0f : (g_si[g_idx[i]] + g_sj[g_idx[j]] + ant_b[0]);
    }
    out[p] = v;
}

// ---------------- launch -----------------------------------------------------
extern "C" void kernel_launch(void* const* d_in, const int* in_sizes, int n_in,
                              void* d_out, int out_size) {
    const float* x      = (const float*)d_in[0];
    const int*   edges  = (const int*)  d_in[1];
    const float* gcn_W  = (const float*)d_in[2];
    const float* gcn_b  = (const float*)d_in[3];
    const float* attn_w = (const float*)d_in[4];
    const float* attn_b = (const float*)d_in[5];
    const float* ms_W1  = (const float*)d_in[6];
    const float* ms_b1  = (const float*)d_in[7];
    const float* ms_W2  = (const float*)d_in[8];
    const float* ms_b2  = (const float*)d_in[9];
    const float* ant_W  = (const float*)d_in[10];
    const float* ant_b  = (const float*)d_in[11];
    const int*   ssp    = (const int*)  d_in[12];
    const int*   sep    = (const int*)  d_in[13];

    int E = in_sizes[1] / 3;
    int Nspan = in_sizes[12];
    int Ktop = (int)((sqrt(1.0 + 4.0 * (double)out_size) - 1.0) / 2.0 + 0.5);

    void* cnt_p;
    cudaGetSymbolAddress(&cnt_p, g_cnt);
    cudaMemsetAsync(cnt_p, 0, sizeof(float) * S_LEN * L_LAB);

    void *xhi, *xlo, *bhi, *blo, *w1h, *w1l, *ehi, *elo, *tf, *embf, *pf;
    cudaGetSymbolAddress(&xhi, g_Xhi);  cudaGetSymbolAddress(&xlo, g_Xlo);
    cudaGetSymbolAddress(&bhi, g_Bhi);  cudaGetSymbolAddress(&blo, g_Blo);
    cudaGetSymbolAddress(&w1h, g_W1thi); cudaGetSymbolAddress(&w1l, g_W1tlo);
    cudaGetSymbolAddress(&ehi, g_Ehi);  cudaGetSymbolAddress(&elo, g_Elo);
    cudaGetSymbolAddress(&tf, g_T);
    cudaGetSymbolAddress(&embf, g_emb);
    cudaGetSymbolAddress(&pf, g_P);

    const int GEMM_SMEM = 2 * 4 * 128 * LDK2 * 2;   // 81920 bytes
    cudaFuncSetAttribute(mma_gemm_kernel, cudaFuncAttributeMaxDynamicSharedMemorySize, GEMM_SMEM);
    cudaFuncSetAttribute(sort2_kernel, cudaFuncAttributeMaxDynamicSharedMemorySize, 65536);
    const int MEN_SMEM = 11 * D_DIM * 4;            // 101376 bytes
    cudaFuncSetAttribute(mention2_kernel, cudaFuncAttributeMaxDynamicSharedMemorySize, MEN_SMEM);

    // edge bucketing + counts
    cnt_kernel<<<(E + 255) / 256, 256>>>(edges, E);
    scan_kernel<<<1, 1024>>>();
    place_kernel<<<(E + 255) / 256, 256>>>(edges, E);

    // weight preprocessing
    transpose_split_kernel<<<dim3(H_DIM / 32, H_DIM / 32, L_LAB), dim3(32, 32)>>>(
        gcn_W, (__nv_bfloat16*)bhi, (__nv_bfloat16*)blo, H_DIM, H_DIM);
    transpose_split_kernel<<<dim3(D_DIM / 32, D_DIM / 32, 1), dim3(32, 32)>>>(
        ms_W1, (__nv_bfloat16*)w1h, (__nv_bfloat16*)w1l, D_DIM, D_DIM);

    cvt_split_kernel<<<(S_LEN * H_DIM / 4 + 255) / 256, 256>>>(
        x, (__nv_bfloat16*)xhi, (__nv_bfloat16*)xlo, S_LEN * H_DIM / 4);

    // GEMM_T: T[l] = x @ W_l^T
    mma_gemm_kernel<<<dim3(H_DIM / 128, S_LEN / 128, L_LAB), 256, GEMM_SMEM>>>(
        (const __nv_bfloat16*)xhi, (const __nv_bfloat16*)xlo,
        (const __nv_bfloat16*)bhi, (const __nv_bfloat16*)blo,
        (float*)tf, H_DIM, H_DIM, H_DIM,
        H_DIM / KT2, 0LL, (long long)H_DIM * H_DIM, (long long)S_LEN * H_DIM, 0);

    gather_kernel<<<S_LEN, H_DIM / 4>>>(0);

    gcn_epi_kernel<<<S_LEN, 256>>>(x, gcn_b);

    cvt_split_kernel<<<(S_LEN * H_DIM / 4 + 255) / 256, 256>>>(
        (const float*)embf, (__nv_bfloat16*)ehi, (__nv_bfloat16*)elo, S_LEN * H_DIM / 4);

    // GEMM_P: P[t] = emb @ W1_block_t
    mma_gemm_kernel<<<dim3(D_DIM / 128, S_LEN / 128, 3), 256, GEMM_SMEM>>>(
        (const __nv_bfloat16*)ehi, (const __nv_bfloat16*)elo,
        (const __nv_bfloat16*)w1h, (const __nv_bfloat16*)w1l,
        (float*)pf, H_DIM, D_DIM, D_DIM,
        H_DIM / KT2, 0LL, (long long)H_DIM, (long long)S_LEN * D_DIM, 0);

    qdot_kernel<<<(7 * S_LEN * 32 + 255) / 256, 256>>>(ant_W, attn_w);
    span_kernel<<<(Nspan + 255) / 256, 256>>>(ssp, sep, attn_b, Nspan);
    mention2_kernel<<<S_LEN - 1, 256, MEN_SMEM>>>(ms_b1, ms_W2, ms_b2);
    sort1_kernel<<<16, 1024>>>(Nspan);
    sort2_kernel<<<1, 1024, 65536>>>(Ktop);
    final_kernel<<<(out_size + 255) / 256, 256>>>(ant_b, (float*)d_out, Ktop, out_size);
}

// round 8
// speedup vs baseline: 1.5589x; 1.5589x over previous
#include <cuda_runtime.h>
#include <cuda_bf16.h>
#include <math.h>
#include <stdint.h>

// ---------------- problem constants ----------------
#define S_LEN 1024
#define H_DIM 768
#define L_LAB 50
#define SW_WIN 10
#define D_DIM 2304            // 3*H
#define NMAX 16384
#define KT2 32                // K per pipeline stage
#define LDK2 40               // padded smem row (elems)
#define KEEP 416

// ---------------- scratch (device globals) ----------------
__device__ float g_T[L_LAB*S_LEN*H_DIM];     // per-label transformed x
__device__ float g_cnt[S_LEN*L_LAB];
__device__ float g_out1[S_LEN*H_DIM];
__device__ float g_emb[S_LEN*H_DIM];
__device__ float g_P[3*S_LEN*D_DIM];
__device__ float g_q[7*S_LEN];
__device__ float g_aw[NMAX*SW_WIN];
__device__ float g_si[NMAX];
__device__ float g_sj[NMAX];
__device__ float g_ms[NMAX];
__device__ int   g_idx[1024];
__device__ unsigned long long g_skeys[16*KEEP];
__device__ int   g_estart[1025];
__device__ int   g_ecur[1024];
__device__ int   g_epack[1 << 17];           // packed T-row index per edge (bucketed by tgt)

__device__ __nv_bfloat16 g_Xhi[S_LEN*H_DIM];
__device__ __nv_bfloat16 g_Xlo[S_LEN*H_DIM];
__device__ __nv_bfloat16 g_Bhi[L_LAB*H_DIM*H_DIM];   // W_l^T per label [l][d][h]
__device__ __nv_bfloat16 g_Blo[L_LAB*H_DIM*H_DIM];
__device__ __nv_bfloat16 g_W1thi[D_DIM*D_DIM];       // ms_W1^T [n][k]
__device__ __nv_bfloat16 g_W1tlo[D_DIM*D_DIM];
__device__ __nv_bfloat16 g_Ehi[S_LEN*H_DIM];
__device__ __nv_bfloat16 g_Elo[S_LEN*H_DIM];

// ---------------- cp.async helpers ----------------
#define CP_ASYNC16(saddr, gptr) \
    asm volatile("cp.async.cg.shared.global [%0], [%1], 16;" :: "r"(saddr), "l"(gptr) : "memory")
#define CP_COMMIT() asm volatile("cp.async.commit_group;" ::: "memory")
#define CP_WAIT1()  asm volatile("cp.async.wait_group 1;" ::: "memory")
#define CP_WAIT0()  asm volatile("cp.async.wait_group 0;" ::: "memory")

__device__ __forceinline__ void mma16816(float* c, const uint32_t* a, const uint32_t* b) {
    asm volatile("mma.sync.aligned.m16n8k16.row.col.f32.bf16.bf16.f32 "
        "{%0,%1,%2,%3}, {%4,%5,%6,%7}, {%8,%9}, {%0,%1,%2,%3};"
        : "+f"(c[0]), "+f"(c[1]), "+f"(c[2]), "+f"(c[3])
        : "r"(a[0]), "r"(a[1]), "r"(a[2]), "r"(a[3]), "r"(b[0]), "r"(b[1]));
}

__device__ __forceinline__ uint32_t pack_bf2(float a, float b) {
    __nv_bfloat162 p(__float2bfloat16_rn(a), __float2bfloat16_rn(b));
    return *(uint32_t*)&p;
}

// ---------------- edge bucketing ----------------
__global__ void cnt_kernel(const int* __restrict__ edges, int E) {
    int e = blockIdx.x * blockDim.x + threadIdx.x;
    if (e >= E) return;
    atomicAdd(&g_cnt[edges[3*e + 1] * L_LAB + edges[3*e + 2]], 1.0f);
}

// per-tgt histogram from g_cnt row sums + exclusive scan
__global__ void scan_kernel() {
    __shared__ int sh[1024];
    int tid = threadIdx.x;
    float fv = 0.f;
#pragma unroll
    for (int l = 0; l < L_LAB; l++) fv += g_cnt[tid * L_LAB + l];
    int v = (int)(fv + 0.5f);
    sh[tid] = v;
    __syncthreads();
    for (int off = 1; off < 1024; off <<= 1) {
        int t = (tid >= off) ? sh[tid - off] : 0;
        __syncthreads();
        sh[tid] += t;
        __syncthreads();
    }
    g_estart[tid + 1] = sh[tid];
    if (tid == 0) g_estart[0] = 0;
    g_ecur[tid] = sh[tid] - v;    // bucket cursor (exclusive prefix)
}

__global__ void place_kernel(const int* __restrict__ edges, int E) {
    int e = blockIdx.x * blockDim.x + threadIdx.x;
    if (e >= E) return;
    int pos = atomicAdd(&g_ecur[edges[3*e + 1]], 1);
    g_epack[pos] = edges[3*e + 2] * S_LEN + edges[3*e];   // T row = lbl*1024 + src
}

// ---------------- fp32 -> bf16 hi/lo split ----------------
__global__ void cvt_split_kernel(const float* __restrict__ src,
                                 __nv_bfloat16* __restrict__ hi,
                                 __nv_bfloat16* __restrict__ lo, int n4) {
    int i = blockIdx.x * blockDim.x + threadIdx.x;
    if (i >= n4) return;
    float4 v = ((const float4*)src)[i];
    float h0f = __bfloat162float(__float2bfloat16_rn(v.x));
    float h1f = __bfloat162float(__float2bfloat16_rn(v.y));
    float h2f = __bfloat162float(__float2bfloat16_rn(v.z));
    float h3f = __bfloat162float(__float2bfloat16_rn(v.w));
    uint2 hv = make_uint2(pack_bf2(v.x, v.y), pack_bf2(v.z, v.w));
    uint2 lv = make_uint2(pack_bf2(v.x - h0f, v.y - h1f), pack_bf2(v.z - h2f, v.w - h3f));
    ((uint2*)hi)[i] = hv;
    ((uint2*)lo)[i] = lv;
}

// ---- fast batched transpose+split: src[b][r][c] -> dst[b][c][r] ------------
// 64x64 tiles, float4 loads, uint2 (2x bf16x2) stores. R, C multiples of 64.
__global__ void transpose_split64_kernel(const float* __restrict__ src,
                                         __nv_bfloat16* __restrict__ hi,
                                         __nv_bfloat16* __restrict__ lo,
                                         int R, int C) {
    __shared__ float t[64][65];
    int b = blockIdx.z;
    int c0 = blockIdx.x * 64, r0 = blockIdx.y * 64;
    int tx = threadIdx.x, ty = threadIdx.y;   // 16 x 16
    size_t sbase = (size_t)b * R * C;

#pragma unroll
    for (int i = 0; i < 4; i++) {
        int row = ty * 4 + i;
        float4 v = *(const float4*)(src + sbase + (size_t)(r0 + row) * C + c0 + tx * 4);
        t[row][tx * 4 + 0] = v.x;
        t[row][tx * 4 + 1] = v.y;
        t[row][tx * 4 + 2] = v.z;
        t[row][tx * 4 + 3] = v.w;
    }
    __syncthreads();

#pragma unroll
    for (int i = 0; i < 4; i++) {
        int oc = ty * 4 + i;                 // output row (original col)
        int orr = tx * 4;                    // output elem base (original row)
        float v0 = t[orr + 0][oc];
        float v1 = t[orr + 1][oc];
        float v2 = t[orr + 2][oc];
        float v3 = t[orr + 3][oc];
        float h0f = __bfloat162float(__float2bfloat16_rn(v0));
        float h1f = __bfloat162float(__float2bfloat16_rn(v1));
        float h2f = __bfloat162float(__float2bfloat16_rn(v2));
        float h3f = __bfloat162float(__float2bfloat16_rn(v3));
        uint2 hv = make_uint2(pack_bf2(v0, v1), pack_bf2(v2, v3));
        uint2 lv = make_uint2(pack_bf2(v0 - h0f, v1 - h1f), pack_bf2(v2 - h2f, v3 - h3f));
        size_t o = sbase + (size_t)(c0 + oc) * R + r0 + orr;
        *(uint2*)(hi + o) = hv;
        *(uint2*)(lo + o) = lv;
    }
}

// ---------------- mma.sync bf16 split GEMM (cp.async, scalar LDS frags) -----
// C[bz*cOff + (bm*128+r)*ldC + bn*128+c] (+)= A(128 x K) * B(128 x K)^T
__global__ __launch_bounds__(256, 2)
void mma_gemm_kernel(const __nv_bfloat16* __restrict__ Ahi, const __nv_bfloat16* __restrict__ Alo,
                     const __nv_bfloat16* __restrict__ Bhi, const __nv_bfloat16* __restrict__ Blo,
                     float* __restrict__ C, int ldA, int ldB, int ldC,
                     int ktiles, long long aOff, long long bOff, long long cOff, int atomic) {
    extern __shared__ __nv_bfloat16 sm[];   // 2 stages x 4 arrays x 128*LDK2
    uint32_t smb = (uint32_t)__cvta_generic_to_shared(sm);

    int tid = threadIdx.x;
    int wid = tid >> 5, lane = tid & 31;
    int wm = wid >> 2, wn = wid & 3;        // warp grid 2x4, warp tile 64x32
    int bn = blockIdx.x, bm = blockIdx.y, bz = blockIdx.z;

    const __nv_bfloat16* Ah = Ahi + (size_t)bm * 128 * ldA + (size_t)bz * aOff;
    const __nv_bfloat16* Al = Alo + (size_t)bm * 128 * ldA + (size_t)bz * aOff;
    const __nv_bfloat16* Bh = Bhi + (size_t)bn * 128 * ldB + (size_t)bz * bOff;
    const __nv_bfloat16* Bl = Blo + (size_t)bn * 128 * ldB + (size_t)bz * bOff;

    float acc[4][4][4];
#pragma unroll
    for (int i = 0; i < 4; i++)
#pragma unroll
        for (int j = 0; j < 4; j++)
#pragma unroll
            for (int r = 0; r < 4; r++) acc[i][j][r] = 0.f;

    const int STAGE = 4 * 128 * LDK2;       // elems per stage

#define ISSUE(stg, t) do {                                                     \
        int k0 = (t) * KT2;                                                    \
        uint32_t sbase = smb + (stg) * STAGE * 2;                              \
        _Pragma("unroll")                                                      \
        for (int i = 0; i < 8; i++) {                                          \
            int o = tid + i * 256;                                             \
            int arr = o >> 9;                                                  \
            int rem = o & 511;                                                 \
            int row = rem >> 2;                                                \
            int quad = rem & 3;                                                \
            const __nv_bfloat16* src; int ld;                                  \
            if (arr == 0)      { src = Ah; ld = ldA; }                         \
            else if (arr == 1) { src = Al; ld = ldA; }                         \
            else if (arr == 2) { src = Bh; ld = ldB; }                         \
            else               { src = Bl; ld = ldB; }                         \
            const void* g = src + (size_t)row * ld + k0 + quad * 8;            \
            uint32_t sa = sbase + (uint32_t)(arr * 128 * LDK2 + row * LDK2 + quad * 8) * 2; \
            CP_ASYNC16(sa, g);                                                 \
        }                                                                      \
    } while (0)

    ISSUE(0, 0);
    CP_COMMIT();

    for (int t = 0; t < ktiles; t++) {
        int s = t & 1;
        if (t + 1 < ktiles) {
            ISSUE(s ^ 1, t + 1);
            CP_COMMIT();
            CP_WAIT1();
        } else {
            CP_WAIT0();
        }
        __syncthreads();

        const __nv_bfloat16* pAh = sm + s * STAGE;
        const __nv_bfloat16* pAl = pAh + 128 * LDK2;
        const __nv_bfloat16* pBh = pAh + 2 * 128 * LDK2;
        const __nv_bfloat16* pBl = pAh + 3 * 128 * LDK2;

#pragma unroll
        for (int ks = 0; ks < 2; ks++) {
            int kk = ks * 16 + (lane & 3) * 2;
            uint32_t ah[4][4], al[4][4], bh[4][2], bl[4][2];
#pragma unroll
            for (int mi = 0; mi < 4; mi++) {
                int row = wm * 64 + mi * 16 + (lane >> 2);
                ah[mi][0] = *(const uint32_t*)&pAh[row * LDK2 + kk];
                ah[mi][1] = *(const uint32_t*)&pAh[(row + 8) * LDK2 + kk];
                ah[mi][2] = *(const uint32_t*)&pAh[row * LDK2 + kk + 8];
                ah[mi][3] = *(const uint32_t*)&pAh[(row + 8) * LDK2 + kk + 8];
                al[mi][0] = *(const uint32_t*)&pAl[row * LDK2 + kk];
                al[mi][1] = *(const uint32_t*)&pAl[(row + 8) * LDK2 + kk];
                al[mi][2] = *(const uint32_t*)&pAl[row * LDK2 + kk + 8];
                al[mi][3] = *(const uint32_t*)&pAl[(row + 8) * LDK2 + kk + 8];
            }
#pragma unroll
            for (int ni = 0; ni < 4; ni++) {
                int nrow = wn * 32 + ni * 8 + (lane >> 2);
                bh[ni][0] = *(const uint32_t*)&pBh[nrow * LDK2 + kk];
                bh[ni][1] = *(const uint32_t*)&pBh[nrow * LDK2 + kk + 8];
                bl[ni][0] = *(const uint32_t*)&pBl[nrow * LDK2 + kk];
                bl[ni][1] = *(const uint32_t*)&pBl[nrow * LDK2 + kk + 8];
            }
#pragma unroll
            for (int mi = 0; mi < 4; mi++)
#pragma unroll
                for (int ni = 0; ni < 4; ni++) {
                    mma16816(acc[mi][ni], ah[mi], bh[ni]);
                    mma16816(acc[mi][ni], ah[mi], bl[ni]);
                    mma16816(acc[mi][ni], al[mi], bh[ni]);
                }
        }
        __syncthreads();
    }

    float* Cb = C + (size_t)bz * cOff + (size_t)bm * 128 * ldC + (size_t)bn * 128;
#pragma unroll
    for (int mi = 0; mi < 4; mi++) {
#pragma unroll
        for (int ni = 0; ni < 4; ni++) {
            int r = wm * 64 + mi * 16 + (lane >> 2);
            int cc = wn * 32 + ni * 8 + (lane & 3) * 2;
            float* p0 = Cb + (size_t)r * ldC + cc;
            float* p1 = Cb + (size_t)(r + 8) * ldC + cc;
            if (atomic) {
                atomicAdd(p0,     acc[mi][ni][0]);
                atomicAdd(p0 + 1, acc[mi][ni][1]);
                atomicAdd(p1,     acc[mi][ni][2]);
                atomicAdd(p1 + 1, acc[mi][ni][3]);
            } else {
                *(float2*)p0 = make_float2(acc[mi][ni][0], acc[mi][ni][1]);
                *(float2*)p1 = make_float2(acc[mi][ni][2], acc[mi][ni][3]);
            }
        }
    }
#undef ISSUE
}

// ---------------- gather: out1[s] = sum_e T[row_e] (packed rows) ------------
__global__ void gather_kernel(int dummy) {
    int s = blockIdx.x;
    int tid = threadIdx.x;  // 192 (= 768/4)
    int beg = g_estart[s], end = g_estart[s + 1];
    float4 acc = make_float4(0.f, 0.f, 0.f, 0.f);
    int p = beg;
    for (; p + 4 <= end; p += 4) {
        int r0 = g_epack[p], r1 = g_epack[p + 1], r2 = g_epack[p + 2], r3 = g_epack[p + 3];
        float4 v0 = __ldg(((const float4*)(g_T + (size_t)r0 * H_DIM)) + tid);
        float4 v1 = __ldg(((const float4*)(g_T + (size_t)r1 * H_DIM)) + tid);
        float4 v2 = __ldg(((const float4*)(g_T + (size_t)r2 * H_DIM)) + tid);
        float4 v3 = __ldg(((const float4*)(g_T + (size_t)r3 * H_DIM)) + tid);
        acc.x += (v0.x + v1.x) + (v2.x + v3.x);
        acc.y += (v0.y + v1.y) + (v2.y + v3.y);
        acc.z += (v0.z + v1.z) + (v2.z + v3.z);
        acc.w += (v0.w + v1.w) + (v2.w + v3.w);
    }
    for (; p < end; p++) {
        int r0 = g_epack[p];
        float4 v0 = __ldg(((const float4*)(g_T + (size_t)r0 * H_DIM)) + tid);
        acc.x += v0.x; acc.y += v0.y; acc.z += v0.z; acc.w += v0.w;
    }
    ((float4*)(g_out1 + (size_t)s * H_DIM))[tid] = acc;
}

// ---------------- GCN epilogue ----------------
__global__ void gcn_epi_kernel(const float* __restrict__ x,
                               const float* __restrict__ gcn_b) {
    int s = blockIdx.x, tid = threadIdx.x;
    __shared__ float c[L_LAB];
    if (tid < L_LAB) c[tid] = g_cnt[s * L_LAB + tid];
    __syncthreads();
    float deg = 0.f;
#pragma unroll
    for (int l = 0; l < L_LAB; l++) deg += c[l];
    deg = fmaxf(deg, 1.0f);
    float inv = 1.0f / deg;
    for (int d = tid; d < H_DIM; d += blockDim.x) {
        float bias = 0.f;
#pragma unroll
        for (int l = 0; l < L_LAB; l++) bias += c[l] * gcn_b[l * H_DIM + d];
        float v = (g_out1[s * H_DIM + d] + bias) * inv;
        g_emb[s * H_DIM + d] = x[s * H_DIM + d] + fmaxf(v, 0.f);
    }
}

// ---------------- q tables ----------------
__global__ void qdot_kernel(const float* __restrict__ antW,
                            const float* __restrict__ attn_w) {
    int wid = (blockIdx.x * blockDim.x + threadIdx.x) >> 5;
    int lane = threadIdx.x & 31;
    if (wid >= 7 * S_LEN) return;
    int t = wid >> 10;
    int s = wid & 1023;
    const float* v = (t < 6) ? (antW + t * H_DIM) : attn_w;
    float p = 0.f;
    for (int h = lane; h < H_DIM; h += 32) p += g_emb[s * H_DIM + h] * v[h];
#pragma unroll
    for (int off = 16; off; off >>= 1) p += __shfl_xor_sync(0xffffffffu, p, off);
    if (lane == 0) g_q[t * S_LEN + s] = p;
}

// ---------------- span attention from score table ---------------------------
__global__ void span_kernel(const int* __restrict__ ssp, const int* __restrict__ sep,
                            const float* __restrict__ attn_b, int Nspan) {
    int n = blockIdx.x * blockDim.x + threadIdx.x;
    if (n >= Nspan) return;
    int ss = ssp[n], se = sep[n];
    float sc[SW_WIN];
#pragma unroll
    for (int w = 0; w < SW_WIN; w++) {
        int pos = ss + w;
        int pc = min(pos, S_LEN - 1);
        sc[w] = (pos <= se) ? (g_q[6 * S_LEN + pc] + attn_b[0]) : -1e9f;
    }
    float mx = sc[0];
#pragma unroll
    for (int w = 1; w < SW_WIN; w++) mx = fmaxf(mx, sc[w]);
    float aw[SW_WIN], Z = 0.f;
#pragma unroll
    for (int w = 0; w < SW_WIN; w++) { aw[w] = expf(sc[w] - mx); Z += aw[w]; }
    float inv = 1.0f / Z;
#pragma unroll
    for (int w = 0; w < SW_WIN; w++) aw[w] *= inv;
    float si = g_q[0 * S_LEN + ss] + g_q[1 * S_LEN + se];
    float sj = g_q[3 * S_LEN + ss] + g_q[4 * S_LEN + se];
#pragma unroll
    for (int w = 0; w < SW_WIN; w++) {
        g_aw[n * SW_WIN + w] = aw[w];
        int pc = min(ss + w, S_LEN - 1);
        si += aw[w] * g_q[2 * S_LEN + pc];
        sj += aw[w] * g_q[5 * S_LEN + pc];
    }
    g_si[n] = si;
    g_sj[n] = sj;
}

// ---------------- mention scores, grouped by span start ---------------------
__global__ void mention2_kernel(const float* __restrict__ b1,
                                const float* __restrict__ W2,
                                const float* __restrict__ b2) {
    int s = blockIdx.x;
    int tid = threadIdx.x;      // 256
    extern __shared__ float sh[];
    float* sP3 = sh;                    // [10][D_DIM]
    float* sP1 = sh + 10 * D_DIM;       // [D_DIM]
    __shared__ float red[8];

    const float4* P3base = (const float4*)(g_P + (size_t)2 * S_LEN * D_DIM);
#pragma unroll
    for (int w = 0; w < SW_WIN; w++) {
        int pc = min(s + w, S_LEN - 1);
        const float4* srcp = P3base + (size_t)pc * (D_DIM / 4);
        float4* dstp = (float4*)(sP3 + w * D_DIM);
        for (int j = tid; j < D_DIM / 4; j += 256) dstp[j] = srcp[j];
    }
    {
        const float4* srcp = (const float4*)(g_P + (size_t)s * D_DIM);
        float4* dstp = (float4*)sP1;
        for (int j = tid; j < D_DIM / 4; j += 256) dstp[j] = srcp[j];
    }
    __syncthreads();

    int nsp, base;
    if (s <= 1014) { nsp = 9; base = 9 * s; }
    else { int u = s - 1015; nsp = 1023 - s; base = 9135 + u * (17 - u) / 2; }

    for (int sp = 0; sp < nsp; sp++) {
        int n = base + sp;
        int e = s + 1 + sp;
        float aw[SW_WIN];
#pragma unroll
        for (int w = 0; w < SW_WIN; w++) aw[w] = g_aw[n * SW_WIN + w];
        const float* P2 = g_P + ((size_t)S_LEN + e) * D_DIM;
        float part = 0.f;
        for (int j = tid; j < D_DIM; j += 256) {
            float v = sP1[j] + P2[j] + b1[j];
#pragma unroll
            for (int w = 0; w < SW_WIN; w++) v += aw[w] * sP3[w * D_DIM + j];
            part += fmaxf(v, 0.f) * W2[j];
        }
#pragma unroll
        for (int off = 16; off; off >>= 1) part += __shfl_xor_sync(0xffffffffu, part, off);
        if ((tid & 31) == 0) red[tid >> 5] = part;
        __syncthreads();
        if (tid < 8) {
            float v2 = red[tid];
#pragma unroll
            for (int off = 4; off; off >>= 1) v2 += __shfl_xor_sync(0xffu, v2, off);
            if (tid == 0) g_ms[n] = v2 + b2[0];
        }
        __syncthreads();
    }
}

// ---------------- top-k: two-stage bitonic ----------------------------------
__device__ __forceinline__ unsigned long long enc_key(float f, int i) {
    unsigned u = __float_as_uint(f);
    unsigned m = (u & 0x80000000u) ? ~u : (u | 0x80000000u);
    return (((unsigned long long)(~m)) << 32) | (unsigned)i;
}

__global__ void sort1_kernel(int Nspan) {
    __shared__ unsigned long long k[1024];
    int b = blockIdx.x, tid = threadIdx.x;
    int i = b * 1024 + tid;
    k[tid] = (i < Nspan) ? enc_key(g_ms[i], i) : ~0ull;
    __syncthreads();
    for (int sz = 2; sz <= 1024; sz <<= 1) {
        for (int j = sz >> 1; j; j >>= 1) {
            int ixj = tid ^ j;
            if (ixj > tid) {
                bool up = ((tid & sz) == 0);
                unsigned long long a = k[tid], c = k[ixj];
                if ((a > c) == up) { k[tid] = c; k[ixj] = a; }
            }
            __syncthreads();
        }
    }
    if (tid < KEEP) g_skeys[b * KEEP + tid] = k[tid];
}

__global__ void sort2_kernel(int Ktop) {
    extern __shared__ unsigned long long k2[];
    const int n = 8192;
    int tid = threadIdx.x;
    for (int i = tid; i < n; i += 1024)
        k2[i] = (i < 16 * KEEP) ? g_skeys[i] : ~0ull;
    __syncthreads();
    for (int sz = 2; sz <= n; sz <<= 1) {
        for (int j = sz >> 1; j; j >>= 1) {
            for (int i = tid; i < n; i += 1024) {
                int ixj = i ^ j;
                if (ixj > i) {
                    bool up = ((i & sz) == 0);
                    unsigned long long a = k2[i], c = k2[ixj];
                    if ((a > c) == up) { k2[i] = c; k2[ixj] = a; }
                }
            }
            __syncthreads();
        }
    }
    for (int i = tid; i < Ktop; i += 1024) g_idx[i] = (int)(k2[i] & 0xFFFFFFFFu);
}

// ---------------- final antecedent matrix -----------------------------------
__global__ void final_kernel(const float* __restrict__ ant_b, float* __restrict__ out,
                             int Ktop, int total) {
    int p = blockIdx.x * blockDim.x + threadIdx.x;
    if (p >= total) return;
    int cols = Ktop + 1;
    int i = p / cols;
    int c = p - i * cols;
    float v;
    if (c == 0) v = 0.0f;
    else {
        int j = c - 1;
        v = (j >= i) ? -10000.0f : (g_si[g_idx[i]] + g_sj[g_idx[j]] + ant_b[0]);
    }
    out[p] = v;
}

// ---------------- launch -----------------------------------------------------
extern "C" void kernel_launch(void* const* d_in, const int* in_sizes, int n_in,
                              void* d_out, int out_size) {
    const float* x      = (const float*)d_in[0];
    const int*   edges  = (const int*)  d_in[1];
    const float* gcn_W  = (const float*)d_in[2];
    const float* gcn_b  = (const float*)d_in[3];
    const float* attn_w = (const float*)d_in[4];
    const float* attn_b = (const float*)d_in[5];
    const float* ms_W1  = (const float*)d_in[6];
    const float* ms_b1  = (const float*)d_in[7];
    const float* ms_W2  = (const float*)d_in[8];
    const float* ms_b2  = (const float*)d_in[9];
    const float* ant_W  = (const float*)d_in[10];
    const float* ant_b  = (const float*)d_in[11];
    const int*   ssp    = (const int*)  d_in[12];
    const int*   sep    = (const int*)  d_in[13];

    int E = in_sizes[1] / 3;
    int Nspan = in_sizes[12];
    int Ktop = (int)((sqrt(1.0 + 4.0 * (double)out_size) - 1.0) / 2.0 + 0.5);

    void* cnt_p;
    cudaGetSymbolAddress(&cnt_p, g_cnt);
    cudaMemsetAsync(cnt_p, 0, sizeof(float) * S_LEN * L_LAB);

    void *xhi, *xlo, *bhi, *blo, *w1h, *w1l, *ehi, *elo, *tf, *embf, *pf;
    cudaGetSymbolAddress(&xhi, g_Xhi);  cudaGetSymbolAddress(&xlo, g_Xlo);
    cudaGetSymbolAddress(&bhi, g_Bhi);  cudaGetSymbolAddress(&blo, g_Blo);
    cudaGetSymbolAddress(&w1h, g_W1thi); cudaGetSymbolAddress(&w1l, g_W1tlo);
    cudaGetSymbolAddress(&ehi, g_Ehi);  cudaGetSymbolAddress(&elo, g_Elo);
    cudaGetSymbolAddress(&tf, g_T);
    cudaGetSymbolAddress(&embf, g_emb);
    cudaGetSymbolAddress(&pf, g_P);

    const int GEMM_SMEM = 2 * 4 * 128 * LDK2 * 2;   // 81920 bytes
    cudaFuncSetAttribute(mma_gemm_kernel, cudaFuncAttributeMaxDynamicSharedMemorySize, GEMM_SMEM);
    cudaFuncSetAttribute(sort2_kernel, cudaFuncAttributeMaxDynamicSharedMemorySize, 65536);
    const int MEN_SMEM = 11 * D_DIM * 4;            // 101376 bytes
    cudaFuncSetAttribute(mention2_kernel, cudaFuncAttributeMaxDynamicSharedMemorySize, MEN_SMEM);

    // edge bucketing + counts
    cnt_kernel<<<(E + 255) / 256, 256>>>(edges, E);
    scan_kernel<<<1, 1024>>>();
    place_kernel<<<(E + 255) / 256, 256>>>(edges, E);

    // weight preprocessing (fast 64x64 tiles)
    transpose_split64_kernel<<<dim3(H_DIM / 64, H_DIM / 64, L_LAB), dim3(16, 16)>>>(
        gcn_W, (__nv_bfloat16*)bhi, (__nv_bfloat16*)blo, H_DIM, H_DIM);
    transpose_split64_kernel<<<dim3(D_DIM / 64, D_DIM / 64, 1), dim3(16, 16)>>>(
        ms_W1, (__nv_bfloat16*)w1h, (__nv_bfloat16*)w1l, D_DIM, D_DIM);

    cvt_split_kernel<<<(S_LEN * H_DIM / 4 + 255) / 256, 256>>>(
        x, (__nv_bfloat16*)xhi, (__nv_bfloat16*)xlo, S_LEN * H_DIM / 4);

    // GEMM_T: T[l] = x @ W_l^T
    mma_gemm_kernel<<<dim3(H_DIM / 128, S_LEN / 128, L_LAB), 256, GEMM_SMEM>>>(
        (const __nv_bfloat16*)xhi, (const __nv_bfloat16*)xlo,
        (const __nv_bfloat16*)bhi, (const __nv_bfloat16*)blo,
        (float*)tf, H_DIM, H_DIM, H_DIM,
        H_DIM / KT2, 0LL, (long long)H_DIM * H_DIM, (long long)S_LEN * H_DIM, 0);

    gather_kernel<<<S_LEN, H_DIM / 4>>>(0);

    gcn_epi_kernel<<<S_LEN, 256>>>(x, gcn_b);

    cvt_split_kernel<<<(S_LEN * H_DIM / 4 + 255) / 256, 256>>>(
        (const float*)embf, (__nv_bfloat16*)ehi, (__nv_bfloat16*)elo, S_LEN * H_DIM / 4);

    // GEMM_P: P[t] = emb @ W1_block_t
    mma_gemm_kernel<<<dim3(D_DIM / 128, S_LEN / 128, 3), 256, GEMM_SMEM>>>(
        (const __nv_bfloat16*)ehi, (const __nv_bfloat16*)elo,
        (const __nv_bfloat16*)w1h, (const __nv_bfloat16*)w1l,
        (float*)pf, H_DIM, D_DIM, D_DIM,
        H_DIM / KT2, 0LL, (long long)H_DIM, (long long)S_LEN * D_DIM, 0);

    qdot_kernel<<<(7 * S_LEN * 32 + 255) / 256, 256>>>(ant_W, attn_w);
    span_kernel<<<(Nspan + 255) / 256, 256>>>(ssp, sep, attn_b, Nspan);
    mention2_kernel<<<S_LEN - 1, 256, MEN_SMEM>>>(ms_b1, ms_W2, ms_b2);
    sort1_kernel<<<16, 1024>>>(Nspan);
    sort2_kernel<<<1, 1024, 65536>>>(Ktop);
    final_kernel<<<(out_size + 255) / 256, 256>>>(ant_b, (float*)d_out, Ktop, out_size);
}